// round 1
// baseline (speedup 1.0000x reference)
#include <cuda_runtime.h>

#define BB   2
#define NP   100000
#define RESO 256
#define HW   65536
#define CINN 64
#define COUTN 128

// -------- scratch (no allocations allowed; __device__ globals) --------
__device__ float g_h1  [BB * COUTN * HW];   // conv1 output (NCHW)
__device__ float g_nhwc[BB * HW * COUTN];   // x_after in NHWC for coalesced sampling
__device__ float g_sums[BB * HW * COUTN];   // scatter sums, [b][pos][ch]
__device__ float g_cnt [BB * HW];           // scatter counts

// =====================================================================
// zero scatter buffers
// =====================================================================
__global__ void zero_kernel() {
    size_t i = (size_t)blockIdx.x * blockDim.x + threadIdx.x;
    size_t stride = (size_t)gridDim.x * blockDim.x;
    float4 z = make_float4(0.f, 0.f, 0.f, 0.f);
    float4* s4 = reinterpret_cast<float4*>(g_sums);
    const size_t n4 = (size_t)BB * HW * COUTN / 4;
    for (size_t k = i; k < n4; k += stride) s4[k] = z;
    for (size_t k = i; k < (size_t)BB * HW; k += stride) g_cnt[k] = 0.f;
}

// =====================================================================
// conv1: 3x3, 64->128, pad 1, relu.  Tile 32x32 spatial, 8 oc / block,
// each thread: 4 y-positions x 8 oc accumulators.
// =====================================================================
__global__ __launch_bounds__(256, 2) void conv1_kernel(
    const float* __restrict__ x, const float* __restrict__ w,
    const float* __restrict__ bias)
{
    __shared__ float tile[34 * 34];
    __shared__ float wsm[72];

    const int tx  = threadIdx.x & 31;
    const int tyb = threadIdx.x >> 5;           // 0..7
    const int x0  = blockIdx.x * 32;
    const int y0  = blockIdx.y * 32;
    const int b   = blockIdx.z >> 4;
    const int oc0 = (blockIdx.z & 15) * 8;

    float acc[4][8];
#pragma unroll
    for (int pp = 0; pp < 4; ++pp)
#pragma unroll
        for (int oc = 0; oc < 8; ++oc) acc[pp][oc] = 0.f;

#pragma unroll 1
    for (int cin = 0; cin < CINN; ++cin) {
        const float* xc = x + ((size_t)(b * CINN + cin)) * HW;
        __syncthreads();
#pragma unroll 1
        for (int i = threadIdx.x; i < 34 * 34; i += 256) {
            int r = i / 34, c = i - r * 34;
            int gy = y0 + r - 1, gx = x0 + c - 1;
            float v = 0.f;
            if ((unsigned)gy < 256u && (unsigned)gx < 256u) v = xc[gy * 256 + gx];
            tile[i] = v;
        }
        if (threadIdx.x < 72)
            wsm[threadIdx.x] =
                w[((size_t)(oc0 + threadIdx.x / 9) * CINN + cin) * 9 + threadIdx.x % 9];
        __syncthreads();

        float iv[4][9];
#pragma unroll
        for (int pp = 0; pp < 4; ++pp) {
            int ry = tyb + pp * 8;
#pragma unroll
            for (int ky = 0; ky < 3; ++ky)
#pragma unroll
                for (int kx = 0; kx < 3; ++kx)
                    iv[pp][ky * 3 + kx] = tile[(ry + ky) * 34 + tx + kx];
        }
#pragma unroll
        for (int oc = 0; oc < 8; ++oc) {
            float wr[9];
#pragma unroll
            for (int k = 0; k < 9; ++k) wr[k] = wsm[oc * 9 + k];
#pragma unroll
            for (int pp = 0; pp < 4; ++pp)
#pragma unroll
                for (int k = 0; k < 9; ++k)
                    acc[pp][oc] += iv[pp][k] * wr[k];
        }
    }

#pragma unroll
    for (int pp = 0; pp < 4; ++pp) {
        int gy = y0 + tyb + pp * 8;
#pragma unroll
        for (int oc = 0; oc < 8; ++oc)
            g_h1[((size_t)(b * COUTN + oc0 + oc)) * HW + gy * 256 + x0 + tx] =
                fmaxf(acc[pp][oc] + bias[oc0 + oc], 0.f);
    }
}

// =====================================================================
// conv2: 3x3 128->128 relu, then + conv1x1(x_after_conv_xy).
// Writes NCHW to d_out x_after region AND NHWC to g_nhwc.
// =====================================================================
__global__ __launch_bounds__(256, 2) void conv2_kernel(
    const float* __restrict__ x2, const float* __restrict__ w2,
    const float* __restrict__ b2, const float* __restrict__ w1x1,
    const float* __restrict__ b1x1, float* __restrict__ xafter)
{
    __shared__ float tile[34 * 34];
    __shared__ float wsm[72];
    __shared__ float w1sm[512];   // 8 oc x 64 cin

    const int tx  = threadIdx.x & 31;
    const int tyb = threadIdx.x >> 5;
    const int x0  = blockIdx.x * 32;
    const int y0  = blockIdx.y * 32;
    const int b   = blockIdx.z >> 4;
    const int oc0 = (blockIdx.z & 15) * 8;

    for (int i = threadIdx.x; i < 512; i += 256)
        w1sm[i] = w1x1[(size_t)(oc0 + (i >> 6)) * CINN + (i & 63)];

    float acc[4][8];
#pragma unroll
    for (int pp = 0; pp < 4; ++pp)
#pragma unroll
        for (int oc = 0; oc < 8; ++oc) acc[pp][oc] = 0.f;

#pragma unroll 1
    for (int cin = 0; cin < COUTN; ++cin) {
        const float* xc = g_h1 + ((size_t)(b * COUTN + cin)) * HW;
        __syncthreads();
#pragma unroll 1
        for (int i = threadIdx.x; i < 34 * 34; i += 256) {
            int r = i / 34, c = i - r * 34;
            int gy = y0 + r - 1, gx = x0 + c - 1;
            float v = 0.f;
            if ((unsigned)gy < 256u && (unsigned)gx < 256u) v = xc[gy * 256 + gx];
            tile[i] = v;
        }
        if (threadIdx.x < 72)
            wsm[threadIdx.x] =
                w2[((size_t)(oc0 + threadIdx.x / 9) * COUTN + cin) * 9 + threadIdx.x % 9];
        __syncthreads();

        float iv[4][9];
#pragma unroll
        for (int pp = 0; pp < 4; ++pp) {
            int ry = tyb + pp * 8;
#pragma unroll
            for (int ky = 0; ky < 3; ++ky)
#pragma unroll
                for (int kx = 0; kx < 3; ++kx)
                    iv[pp][ky * 3 + kx] = tile[(ry + ky) * 34 + tx + kx];
        }
#pragma unroll
        for (int oc = 0; oc < 8; ++oc) {
            float wr[9];
#pragma unroll
            for (int k = 0; k < 9; ++k) wr[k] = wsm[oc * 9 + k];
#pragma unroll
            for (int pp = 0; pp < 4; ++pp)
#pragma unroll
                for (int k = 0; k < 9; ++k)
                    acc[pp][oc] += iv[pp][k] * wr[k];
        }
    }

    // relu(conv2 + b2) then seed with b1x1 for the 1x1 accumulation
#pragma unroll
    for (int pp = 0; pp < 4; ++pp)
#pragma unroll
        for (int oc = 0; oc < 8; ++oc)
            acc[pp][oc] = fmaxf(acc[pp][oc] + b2[oc0 + oc], 0.f) + b1x1[oc0 + oc];

    // fused 1x1 over 64 input channels of x_after_conv_xy
    const float* x2b = x2 + (size_t)b * CINN * HW;
#pragma unroll 1
    for (int cin = 0; cin < CINN; ++cin) {
        __syncthreads();
        for (int i = threadIdx.x; i < 1024; i += 256) {
            int r = i >> 5, c = i & 31;
            tile[i] = x2b[(size_t)cin * HW + (y0 + r) * 256 + x0 + c];
        }
        __syncthreads();
        float v[4];
#pragma unroll
        for (int pp = 0; pp < 4; ++pp) v[pp] = tile[(tyb + pp * 8) * 32 + tx];
#pragma unroll
        for (int oc = 0; oc < 8; ++oc) {
            float wv = w1sm[oc * 64 + cin];
#pragma unroll
            for (int pp = 0; pp < 4; ++pp) acc[pp][oc] += v[pp] * wv;
        }
    }

#pragma unroll
    for (int pp = 0; pp < 4; ++pp) {
        int gy = y0 + tyb + pp * 8;
        size_t sp = (size_t)gy * 256 + x0 + tx;
#pragma unroll
        for (int oc = 0; oc < 8; ++oc)
            xafter[((size_t)(b * COUTN + oc0 + oc)) * HW + sp] = acc[pp][oc];
        float4 o0 = make_float4(acc[pp][0], acc[pp][1], acc[pp][2], acc[pp][3]);
        float4 o1 = make_float4(acc[pp][4], acc[pp][5], acc[pp][6], acc[pp][7]);
        float* nb = g_nhwc + ((size_t)b * HW + sp) * COUTN + oc0;
        reinterpret_cast<float4*>(nb)[0] = o0;
        reinterpret_cast<float4*>(nb)[1] = o1;
    }
}

// =====================================================================
// point kernel: bilinear sample + MLP (fc1 relu, fc2, + c_last@fcc)
// + write c + scatter-add.  64 points per block, 256 threads.
// =====================================================================
#define PK_SMEM 147712

__global__ __launch_bounds__(256) void point_kernel(
    const float* __restrict__ p, const float* __restrict__ c_last,
    const float* __restrict__ w1, const float* __restrict__ bfc1,
    const float* __restrict__ w2, const float* __restrict__ bfc2,
    const float* __restrict__ wcc, const float* __restrict__ bcc,
    float* __restrict__ c_out)
{
    extern __shared__ float sm[];
    float* cbuf = sm;                     // 64*128
    float* h1sm = sm + 8192;              // 64*256
    float* wsm  = sm + 8192 + 16384;      // 8192 floats staging
    float* clsm = wsm + 8192;             // 64*64
    int*   pidx = (int*)(clsm + 4096);    // 64

    const int tid  = threadIdx.x;
    const int lane = tid & 31;
    const int warp = tid >> 5;
    const int b    = blockIdx.y;
    const int n0   = blockIdx.x * 64;

    // ---- Phase A: bilinear sample into cbuf, load c_last, scatter counts
#pragma unroll 1
    for (int it = 0; it < 8; ++it) {
        int pt = warp * 8 + it;
        int n  = n0 + pt;
        if (n < NP) {
            float xf = p[((size_t)b * NP + n) * 3 + 0];
            float yf = p[((size_t)b * NP + n) * 3 + 1];
            float px = fminf(fmaxf(xf * 255.f, 0.f), 255.f);
            float py = fminf(fmaxf(yf * 255.f, 0.f), 255.f);
            float fx = floorf(px), fy = floorf(py);
            int x0i = (int)fx, y0i = (int)fy;
            int x1i = min(x0i + 1, 255), y1i = min(y0i + 1, 255);
            float wx = px - fx, wy = py - fy;
            float w00 = (1.f - wx) * (1.f - wy), w01 = wx * (1.f - wy);
            float w10 = (1.f - wx) * wy,         w11 = wx * wy;
            const float* base = g_nhwc + (size_t)b * HW * COUTN;
            const float4* f00 = (const float4*)(base + (size_t)(y0i * 256 + x0i) * COUTN);
            const float4* f01 = (const float4*)(base + (size_t)(y0i * 256 + x1i) * COUTN);
            const float4* f10 = (const float4*)(base + (size_t)(y1i * 256 + x0i) * COUTN);
            const float4* f11 = (const float4*)(base + (size_t)(y1i * 256 + x1i) * COUTN);
            float4 a = f00[lane], bq = f01[lane], cq = f10[lane], dq = f11[lane];
            float4 r;
            r.x = a.x * w00 + bq.x * w01 + cq.x * w10 + dq.x * w11;
            r.y = a.y * w00 + bq.y * w01 + cq.y * w10 + dq.y * w11;
            r.z = a.z * w00 + bq.z * w01 + cq.z * w10 + dq.z * w11;
            r.w = a.w * w00 + bq.w * w01 + cq.w * w10 + dq.w * w11;
            reinterpret_cast<float4*>(cbuf + pt * 128)[lane] = r;
            float2 cl = reinterpret_cast<const float2*>(c_last + ((size_t)b * NP + n) * 64)[lane];
            reinterpret_cast<float2*>(clsm + pt * 64)[lane] = cl;
            if (lane == 0) {
                int ix = (int)(xf * 256.f); ix = min(max(ix, 0), 255);
                int iy = (int)(yf * 256.f); iy = min(max(iy, 0), 255);
                int idx = ix + (iy << 8);
                pidx[pt] = idx;
                atomicAdd(&g_cnt[b * HW + idx], 1.f);
            }
        } else {
            reinterpret_cast<float4*>(cbuf + pt * 128)[lane] = make_float4(0, 0, 0, 0);
            reinterpret_cast<float2*>(clsm + pt * 64)[lane] = make_float2(0, 0);
            if (lane == 0) pidx[pt] = 0;
        }
    }
    __syncthreads();

    // ---- Stage 1: h1 = relu(c @ W1 + b1)   M=64 N=256 K=128
    float acc[8][8];
#pragma unroll
    for (int i = 0; i < 8; ++i)
#pragma unroll
        for (int j = 0; j < 8; ++j) acc[i][j] = 0.f;

#pragma unroll 1
    for (int kc = 0; kc < 128; kc += 16) {
        const float4* src = (const float4*)(w1 + (size_t)kc * 256);
        float4* dst = (float4*)wsm;
#pragma unroll
        for (int i = 0; i < 4; ++i) dst[tid + 256 * i] = src[tid + 256 * i];
        __syncthreads();
#pragma unroll
        for (int k = 0; k < 16; ++k) {
            float a[8];
#pragma unroll
            for (int i = 0; i < 8; ++i) a[i] = cbuf[(warp * 8 + i) * 128 + kc + k];
            float4 b0 = ((const float4*)(wsm + k * 256))[lane * 2];
            float4 b1 = ((const float4*)(wsm + k * 256))[lane * 2 + 1];
            float bb[8] = {b0.x, b0.y, b0.z, b0.w, b1.x, b1.y, b1.z, b1.w};
#pragma unroll
            for (int i = 0; i < 8; ++i)
#pragma unroll
                for (int j = 0; j < 8; ++j) acc[i][j] += a[i] * bb[j];
        }
        __syncthreads();
    }
    {
        float bia[8];
#pragma unroll
        for (int j = 0; j < 8; ++j) bia[j] = bfc1[lane * 8 + j];
#pragma unroll
        for (int i = 0; i < 8; ++i) {
            int m = warp * 8 + i;
            float4 h0, h1v;
            h0.x = fmaxf(acc[i][0] + bia[0], 0.f);
            h0.y = fmaxf(acc[i][1] + bia[1], 0.f);
            h0.z = fmaxf(acc[i][2] + bia[2], 0.f);
            h0.w = fmaxf(acc[i][3] + bia[3], 0.f);
            h1v.x = fmaxf(acc[i][4] + bia[4], 0.f);
            h1v.y = fmaxf(acc[i][5] + bia[5], 0.f);
            h1v.z = fmaxf(acc[i][6] + bia[6], 0.f);
            h1v.w = fmaxf(acc[i][7] + bia[7], 0.f);
            ((float4*)(h1sm + m * 256))[lane * 2]     = h0;
            ((float4*)(h1sm + m * 256))[lane * 2 + 1] = h1v;
        }
    }
    __syncthreads();

    // ---- Stage 2: out = h1 @ W2 + b2 + c_last @ Wcc + bcc   M=64 N=128
    float4 acc2[8];
    {
        float4 f2 = ((const float4*)bfc2)[lane];
        float4 fc = ((const float4*)bcc)[lane];
        float4 bs = make_float4(f2.x + fc.x, f2.y + fc.y, f2.z + fc.z, f2.w + fc.w);
#pragma unroll
        for (int i = 0; i < 8; ++i) acc2[i] = bs;
    }
#pragma unroll 1
    for (int kc = 0; kc < 256; kc += 32) {
        const float4* src = (const float4*)(w2 + (size_t)kc * 128);
#pragma unroll
        for (int i = 0; i < 4; ++i) ((float4*)wsm)[tid + 256 * i] = src[tid + 256 * i];
        __syncthreads();
#pragma unroll 8
        for (int k = 0; k < 32; ++k) {
            float a[8];
#pragma unroll
            for (int i = 0; i < 8; ++i) a[i] = h1sm[(warp * 8 + i) * 256 + kc + k];
            float4 bv = ((const float4*)(wsm + k * 128))[lane];
#pragma unroll
            for (int i = 0; i < 8; ++i) {
                acc2[i].x += a[i] * bv.x; acc2[i].y += a[i] * bv.y;
                acc2[i].z += a[i] * bv.z; acc2[i].w += a[i] * bv.w;
            }
        }
        __syncthreads();
    }
    {
#pragma unroll
        for (int i = 0; i < 8; ++i) ((float4*)wsm)[tid + 256 * i] = ((const float4*)wcc)[tid + 256 * i];
        __syncthreads();
#pragma unroll 8
        for (int k = 0; k < 64; ++k) {
            float a[8];
#pragma unroll
            for (int i = 0; i < 8; ++i) a[i] = clsm[(warp * 8 + i) * 64 + k];
            float4 bv = ((const float4*)(wsm + k * 128))[lane];
#pragma unroll
            for (int i = 0; i < 8; ++i) {
                acc2[i].x += a[i] * bv.x; acc2[i].y += a[i] * bv.y;
                acc2[i].z += a[i] * bv.z; acc2[i].w += a[i] * bv.w;
            }
        }
    }

    // ---- epilogue: write c, scatter-add sums
#pragma unroll
    for (int i = 0; i < 8; ++i) {
        int pt = warp * 8 + i, n = n0 + pt;
        if (n < NP) {
            reinterpret_cast<float4*>(c_out + ((size_t)b * NP + n) * COUTN)[lane] = acc2[i];
            float* s = g_sums + ((size_t)(b * HW + pidx[pt])) * COUTN + lane * 4;
            atomicAdd(s + 0, acc2[i].x);
            atomicAdd(s + 1, acc2[i].y);
            atomicAdd(s + 2, acc2[i].z);
            atomicAdd(s + 3, acc2[i].w);
        }
    }
}

// =====================================================================
// finalize: plane = sums / max(cnt,1), transpose to NCHW (before_pool),
// fused 2x2 maxpool (out).  Block: 2 rows x 64 cols x 32 channels.
// =====================================================================
__global__ __launch_bounds__(256) void finalize_kernel(
    float* __restrict__ out, float* __restrict__ before)
{
    __shared__ float sd[128][33];
    __shared__ float csm[128];
    const int tid = threadIdx.x;
    const int x0  = blockIdx.x * 64;
    const int y0  = blockIdx.y * 2;
    const int b   = blockIdx.z >> 2;
    const int cg  = blockIdx.z & 3;

    if (tid < 128) {
        int gpos = (y0 + (tid >> 6)) * 256 + x0 + (tid & 63);
        csm[tid] = fmaxf(g_cnt[b * HW + gpos], 1.f);
    }
    __syncthreads();
#pragma unroll
    for (int i = 0; i < 16; ++i) {
        int lin = tid + 256 * i;
        int pos = lin >> 5, ch = lin & 31;
        int gpos = (y0 + (pos >> 6)) * 256 + x0 + (pos & 63);
        sd[pos][ch] = g_sums[((size_t)(b * HW) + gpos) * COUTN + cg * 32 + ch] / csm[pos];
    }
    __syncthreads();
#pragma unroll
    for (int i = 0; i < 16; ++i) {
        int lin = tid + 256 * i;
        int ch = lin >> 7, pos = lin & 127;
        before[((size_t)(b * COUTN + cg * 32 + ch)) * HW +
               (y0 + (pos >> 6)) * 256 + x0 + (pos & 63)] = sd[pos][ch];
    }
    const int oy = y0 >> 1, ox0 = x0 >> 1;
#pragma unroll
    for (int i = 0; i < 4; ++i) {
        int lin = tid + 256 * i;
        int ch = lin >> 5, ox = lin & 31;
        float m = fmaxf(fmaxf(sd[2 * ox][ch], sd[2 * ox + 1][ch]),
                        fmaxf(sd[64 + 2 * ox][ch], sd[64 + 2 * ox + 1][ch]));
        out[((size_t)(b * COUTN + cg * 32 + ch)) * (128 * 128) + oy * 128 + ox0 + ox] = m;
    }
}

// =====================================================================
// launch
// =====================================================================
extern "C" void kernel_launch(void* const* d_in, const int* in_sizes, int n_in,
                              void* d_out, int out_size)
{
    const float* p      = (const float*)d_in[0];
    const float* x_xy   = (const float*)d_in[1];
    const float* x2     = (const float*)d_in[2];
    const float* c_last = (const float*)d_in[3];
    const float* w1c    = (const float*)d_in[4];
    const float* b1c    = (const float*)d_in[5];
    const float* w2c    = (const float*)d_in[6];
    const float* b2c    = (const float*)d_in[7];
    const float* w11    = (const float*)d_in[8];
    const float* b11    = (const float*)d_in[9];
    const float* wf1    = (const float*)d_in[10];
    const float* bf1    = (const float*)d_in[11];
    const float* wf2    = (const float*)d_in[12];
    const float* bf2    = (const float*)d_in[13];
    const float* wcc    = (const float*)d_in[14];
    const float* bcc    = (const float*)d_in[15];

    float* out    = (float*)d_out;                            // [2,128,128,128]
    float* before = out    + (size_t)BB * COUTN * 128 * 128;  // [2,128,256,256]
    float* xafter = before + (size_t)BB * COUTN * HW;         // [2,128,256,256]
    float* cout   = xafter + (size_t)BB * COUTN * HW;         // [2,100000,128]

    zero_kernel<<<2048, 256>>>();

    dim3 cg(8, 8, BB * 16);
    conv1_kernel<<<cg, 256>>>(x_xy, w1c, b1c);
    conv2_kernel<<<cg, 256>>>(x2, w2c, b2c, w11, b11, xafter);

    cudaFuncSetAttribute(point_kernel, cudaFuncAttributeMaxDynamicSharedMemorySize, PK_SMEM);
    dim3 pg((NP + 63) / 64, BB);
    point_kernel<<<pg, 256, PK_SMEM>>>(p, c_last, wf1, bf1, wf2, bf2, wcc, bcc, cout);

    dim3 fg(4, 128, BB * 4);
    finalize_kernel<<<fg, 256>>>(out, before);
}

// round 7
// speedup vs baseline: 2.1451x; 2.1451x over previous
#include <cuda_runtime.h>

#define BB   2
#define NP   100000
#define RESO 256
#define HW   65536
#define CINN 64
#define COUTN 128

// -------- scratch (no allocations allowed; __device__ globals) --------
__device__ float g_h1  [BB * COUTN * HW];   // conv1 output (NCHW)
__device__ float g_nhwc[BB * HW * COUTN];   // x_after in NHWC for coalesced sampling
__device__ float g_sums[BB * HW * COUTN];   // scatter sums, [b][pos][ch]
__device__ float g_cnt [BB * HW];           // scatter counts

// =====================================================================
// zero scatter buffers
// =====================================================================
__global__ void zero_kernel() {
    size_t i = (size_t)blockIdx.x * blockDim.x + threadIdx.x;
    size_t stride = (size_t)gridDim.x * blockDim.x;
    float4 z = make_float4(0.f, 0.f, 0.f, 0.f);
    float4* s4 = reinterpret_cast<float4*>(g_sums);
    const size_t n4 = (size_t)BB * HW * COUTN / 4;
    for (size_t k = i; k < n4; k += stride) s4[k] = z;
    for (size_t k = i; k < (size_t)BB * HW; k += stride) g_cnt[k] = 0.f;
}

// =====================================================================
// 3x3 conv tiles: 32 wide x 64 tall, 8 oc per block, 8 y-rows/thread.
// Double-buffered input tile (66x34), all weights preloaded in smem.
// =====================================================================
#define TILE_ELEMS 2244   // 66 * 34

__device__ __forceinline__ void ldg_tile(const float* __restrict__ xc,
                                         int x0, int y0, int tid, float ld[9]) {
#pragma unroll
    for (int j = 0; j < 9; ++j) {
        int e = tid + 256 * j;
        float v = 0.f;
        if (e < TILE_ELEMS) {
            int r = e / 34, c = e - r * 34;
            int gy = y0 + r - 1, gx = x0 + c - 1;
            if ((unsigned)gy < 256u && (unsigned)gx < 256u)
                v = __ldg(xc + gy * 256 + gx);
        }
        ld[j] = v;
    }
}

__device__ __forceinline__ void sts_tile(float* buf, int tid, const float ld[9]) {
#pragma unroll
    for (int j = 0; j < 9; ++j) {
        int e = tid + 256 * j;
        if (e < TILE_ELEMS) buf[e] = ld[j];
    }
}

// ---------------------------------------------------------------------
// conv1: 3x3, 64->128, pad 1, relu -> g_h1
// ---------------------------------------------------------------------
__global__ __launch_bounds__(256, 2) void conv1_kernel(
    const float* __restrict__ x, const float* __restrict__ w,
    const float* __restrict__ bias)
{
    __shared__ float wall[CINN * 72];
    __shared__ float tile[2][TILE_ELEMS];

    const int tid = threadIdx.x;
    const int tx  = tid & 31;
    const int ry  = (tid >> 5) * 8;
    const int x0  = blockIdx.x * 32;
    const int y0  = blockIdx.y * 64;
    const int b   = blockIdx.z >> 4;
    const int oc0 = (blockIdx.z & 15) * 8;

    for (int i = tid; i < CINN * 72; i += 256) {
        int cin = i / 72, r = i - cin * 72;
        wall[i] = w[((size_t)(oc0 + r / 9) * CINN + cin) * 9 + (r % 9)];
    }
    {
        float ld[9];
        ldg_tile(x + (size_t)(b * CINN) * HW, x0, y0, tid, ld);
        sts_tile(tile[0], tid, ld);
    }
    __syncthreads();

    float acc[8][8];
#pragma unroll
    for (int pp = 0; pp < 8; ++pp)
#pragma unroll
        for (int oc = 0; oc < 8; ++oc) acc[pp][oc] = 0.f;

    int cur = 0;
#pragma unroll 1
    for (int cin = 0; cin < CINN; ++cin) {
        float ld[9];
        const bool have = (cin + 1) < CINN;
        if (have) ldg_tile(x + (size_t)(b * CINN + cin + 1) * HW, x0, y0, tid, ld);

        float xw[10][3];
#pragma unroll
        for (int r = 0; r < 10; ++r)
#pragma unroll
            for (int c = 0; c < 3; ++c)
                xw[r][c] = tile[cur][(ry + r) * 34 + tx + c];

#pragma unroll
        for (int oc = 0; oc < 8; ++oc) {
            float wr[9];
#pragma unroll
            for (int k = 0; k < 9; ++k) wr[k] = wall[cin * 72 + oc * 9 + k];
#pragma unroll
            for (int pp = 0; pp < 8; ++pp)
#pragma unroll
                for (int ky = 0; ky < 3; ++ky)
#pragma unroll
                    for (int kx = 0; kx < 3; ++kx)
                        acc[pp][oc] = fmaf(xw[pp + ky][kx], wr[ky * 3 + kx], acc[pp][oc]);
        }

        if (have) sts_tile(tile[cur ^ 1], tid, ld);
        __syncthreads();
        cur ^= 1;
    }

#pragma unroll
    for (int pp = 0; pp < 8; ++pp) {
        int gy = y0 + ry + pp;
#pragma unroll
        for (int oc = 0; oc < 8; ++oc)
            g_h1[((size_t)(b * COUTN + oc0 + oc)) * HW + gy * 256 + x0 + tx] =
                fmaxf(acc[pp][oc] + bias[oc0 + oc], 0.f);
    }
}

// ---------------------------------------------------------------------
// conv2: 3x3 128->128 relu, + 1x1(x_after_conv_xy). Writes NCHW xafter
// and NHWC copy for sampling.
// ---------------------------------------------------------------------
__global__ __launch_bounds__(256, 2) void conv2_kernel(
    const float* __restrict__ x2, const float* __restrict__ w2,
    const float* __restrict__ b2, const float* __restrict__ w1x1,
    const float* __restrict__ b1x1, float* __restrict__ xafter)
{
    __shared__ float wall[COUTN * 72];
    __shared__ float tile[2][TILE_ELEMS];
    __shared__ float w1sm[512];

    const int tid = threadIdx.x;
    const int tx  = tid & 31;
    const int ry  = (tid >> 5) * 8;
    const int x0  = blockIdx.x * 32;
    const int y0  = blockIdx.y * 64;
    const int b   = blockIdx.z >> 4;
    const int oc0 = (blockIdx.z & 15) * 8;

    for (int i = tid; i < COUTN * 72; i += 256) {
        int cin = i / 72, r = i - cin * 72;
        wall[i] = w2[((size_t)(oc0 + r / 9) * COUTN + cin) * 9 + (r % 9)];
    }
    for (int i = tid; i < 512; i += 256)
        w1sm[i] = w1x1[(size_t)(oc0 + (i >> 6)) * CINN + (i & 63)];
    {
        float ld[9];
        ldg_tile(g_h1 + (size_t)(b * COUTN) * HW, x0, y0, tid, ld);
        sts_tile(tile[0], tid, ld);
    }
    __syncthreads();

    float acc[8][8];
#pragma unroll
    for (int pp = 0; pp < 8; ++pp)
#pragma unroll
        for (int oc = 0; oc < 8; ++oc) acc[pp][oc] = 0.f;

    int cur = 0;
#pragma unroll 1
    for (int cin = 0; cin < COUTN; ++cin) {
        float ld[9];
        const bool have = (cin + 1) < COUTN;
        if (have) ldg_tile(g_h1 + (size_t)(b * COUTN + cin + 1) * HW, x0, y0, tid, ld);

        float xw[10][3];
#pragma unroll
        for (int r = 0; r < 10; ++r)
#pragma unroll
            for (int c = 0; c < 3; ++c)
                xw[r][c] = tile[cur][(ry + r) * 34 + tx + c];

#pragma unroll
        for (int oc = 0; oc < 8; ++oc) {
            float wr[9];
#pragma unroll
            for (int k = 0; k < 9; ++k) wr[k] = wall[cin * 72 + oc * 9 + k];
#pragma unroll
            for (int pp = 0; pp < 8; ++pp)
#pragma unroll
                for (int ky = 0; ky < 3; ++ky)
#pragma unroll
                    for (int kx = 0; kx < 3; ++kx)
                        acc[pp][oc] = fmaf(xw[pp + ky][kx], wr[ky * 3 + kx], acc[pp][oc]);
        }

        if (have) sts_tile(tile[cur ^ 1], tid, ld);
        __syncthreads();
        cur ^= 1;
    }

    // relu(conv2 + b2) then seed with b1x1
#pragma unroll
    for (int oc = 0; oc < 8; ++oc) {
        float bb = b2[oc0 + oc], bs = b1x1[oc0 + oc];
#pragma unroll
        for (int pp = 0; pp < 8; ++pp)
            acc[pp][oc] = fmaxf(acc[pp][oc] + bb, 0.f) + bs;
    }

    // fused 1x1: register-direct from gmem (L2-resident after first oc pass)
    const float* x2p = x2 + (size_t)b * CINN * HW + (size_t)(y0 + ry) * 256 + x0 + tx;
#pragma unroll 2
    for (int cin = 0; cin < CINN; ++cin) {
        float v[8];
#pragma unroll
        for (int pp = 0; pp < 8; ++pp)
            v[pp] = __ldg(x2p + (size_t)cin * HW + pp * 256);
#pragma unroll
        for (int oc = 0; oc < 8; ++oc) {
            float wv = w1sm[oc * 64 + cin];
#pragma unroll
            for (int pp = 0; pp < 8; ++pp)
                acc[pp][oc] = fmaf(v[pp], wv, acc[pp][oc]);
        }
    }

#pragma unroll
    for (int pp = 0; pp < 8; ++pp) {
        int gy = y0 + ry + pp;
        size_t sp = (size_t)gy * 256 + x0 + tx;
#pragma unroll
        for (int oc = 0; oc < 8; ++oc)
            xafter[((size_t)(b * COUTN + oc0 + oc)) * HW + sp] = acc[pp][oc];
        float4 o0 = make_float4(acc[pp][0], acc[pp][1], acc[pp][2], acc[pp][3]);
        float4 o1 = make_float4(acc[pp][4], acc[pp][5], acc[pp][6], acc[pp][7]);
        float* nb = g_nhwc + ((size_t)b * HW + sp) * COUTN + oc0;
        reinterpret_cast<float4*>(nb)[0] = o0;
        reinterpret_cast<float4*>(nb)[1] = o1;
    }
}

// =====================================================================
// point kernel: bilinear sample + MLP + scatter.  64 pts/block.
// smem layout (96.3 KB -> 2 CTAs/SM):
//   [0      , 16384) h1sm (64x256)   -- first 8192 floats double as cbuf
//   [16384  , 20480) wsm  (staging, 16KB)
//   [20480  , 24576) clsm (64x64)
//   [24576  , +64  ) pidx
// =====================================================================
#define PK_SMEM 98560

__global__ __launch_bounds__(256) void point_kernel(
    const float* __restrict__ p, const float* __restrict__ c_last,
    const float* __restrict__ w1, const float* __restrict__ bfc1,
    const float* __restrict__ w2, const float* __restrict__ bfc2,
    const float* __restrict__ wcc, const float* __restrict__ bcc,
    float* __restrict__ c_out)
{
    extern __shared__ float sm[];
    float* h1sm = sm;                     // 64*256
    float* cbuf = sm;                     // 64*128 (overlaid; dead before h1 write)
    float* wsm  = sm + 16384;             // 4096 floats
    float* clsm = sm + 16384 + 4096;      // 64*64
    int*   pidx = (int*)(sm + 24576);     // 64

    const int tid  = threadIdx.x;
    const int lane = tid & 31;
    const int warp = tid >> 5;
    const int b    = blockIdx.y;
    const int n0   = blockIdx.x * 64;

    // ---- Phase A: bilinear sample into cbuf, load c_last, scatter counts
#pragma unroll 1
    for (int it = 0; it < 8; ++it) {
        int pt = warp * 8 + it;
        int n  = n0 + pt;
        if (n < NP) {
            float xf = p[((size_t)b * NP + n) * 3 + 0];
            float yf = p[((size_t)b * NP + n) * 3 + 1];
            float px = fminf(fmaxf(xf * 255.f, 0.f), 255.f);
            float py = fminf(fmaxf(yf * 255.f, 0.f), 255.f);
            float fx = floorf(px), fy = floorf(py);
            int x0i = (int)fx, y0i = (int)fy;
            int x1i = min(x0i + 1, 255), y1i = min(y0i + 1, 255);
            float wx = px - fx, wy = py - fy;
            float w00 = (1.f - wx) * (1.f - wy), w01 = wx * (1.f - wy);
            float w10 = (1.f - wx) * wy,         w11 = wx * wy;
            const float* base = g_nhwc + (size_t)b * HW * COUTN;
            const float4* f00 = (const float4*)(base + (size_t)(y0i * 256 + x0i) * COUTN);
            const float4* f01 = (const float4*)(base + (size_t)(y0i * 256 + x1i) * COUTN);
            const float4* f10 = (const float4*)(base + (size_t)(y1i * 256 + x0i) * COUTN);
            const float4* f11 = (const float4*)(base + (size_t)(y1i * 256 + x1i) * COUTN);
            float4 a = f00[lane], bq = f01[lane], cq = f10[lane], dq = f11[lane];
            float4 r;
            r.x = a.x * w00 + bq.x * w01 + cq.x * w10 + dq.x * w11;
            r.y = a.y * w00 + bq.y * w01 + cq.y * w10 + dq.y * w11;
            r.z = a.z * w00 + bq.z * w01 + cq.z * w10 + dq.z * w11;
            r.w = a.w * w00 + bq.w * w01 + cq.w * w10 + dq.w * w11;
            reinterpret_cast<float4*>(cbuf + pt * 128)[lane] = r;
            float2 cl = reinterpret_cast<const float2*>(c_last + ((size_t)b * NP + n) * 64)[lane];
            reinterpret_cast<float2*>(clsm + pt * 64)[lane] = cl;
            if (lane == 0) {
                int ix = (int)(xf * 256.f); ix = min(max(ix, 0), 255);
                int iy = (int)(yf * 256.f); iy = min(max(iy, 0), 255);
                int idx = ix + (iy << 8);
                pidx[pt] = idx;
                atomicAdd(&g_cnt[b * HW + idx], 1.f);
            }
        } else {
            reinterpret_cast<float4*>(cbuf + pt * 128)[lane] = make_float4(0, 0, 0, 0);
            reinterpret_cast<float2*>(clsm + pt * 64)[lane] = make_float2(0, 0);
            if (lane == 0) pidx[pt] = 0;
        }
    }
    __syncthreads();

    // ---- Stage 1: h1 = relu(c @ W1 + b1)   M=64 N=256 K=128
    float acc[8][8];
#pragma unroll
    for (int i = 0; i < 8; ++i)
#pragma unroll
        for (int j = 0; j < 8; ++j) acc[i][j] = 0.f;

#pragma unroll 1
    for (int kc = 0; kc < 128; kc += 16) {
        const float4* src = (const float4*)(w1 + (size_t)kc * 256);
        float4* dst = (float4*)wsm;
#pragma unroll
        for (int i = 0; i < 4; ++i) dst[tid + 256 * i] = src[tid + 256 * i];
        __syncthreads();
#pragma unroll
        for (int k = 0; k < 16; ++k) {
            float a[8];
#pragma unroll
            for (int i = 0; i < 8; ++i) a[i] = cbuf[(warp * 8 + i) * 128 + kc + k];
            float4 b0 = ((const float4*)(wsm + k * 256))[lane * 2];
            float4 b1 = ((const float4*)(wsm + k * 256))[lane * 2 + 1];
            float bb[8] = {b0.x, b0.y, b0.z, b0.w, b1.x, b1.y, b1.z, b1.w};
#pragma unroll
            for (int i = 0; i < 8; ++i)
#pragma unroll
                for (int j = 0; j < 8; ++j) acc[i][j] += a[i] * bb[j];
        }
        __syncthreads();    // after last chunk: all cbuf reads complete
    }
    // write h1 (overlays cbuf region -- safe, cbuf fully consumed)
    {
        float bia[8];
#pragma unroll
        for (int j = 0; j < 8; ++j) bia[j] = bfc1[lane * 8 + j];
#pragma unroll
        for (int i = 0; i < 8; ++i) {
            int m = warp * 8 + i;
            float4 h0, h1v;
            h0.x = fmaxf(acc[i][0] + bia[0], 0.f);
            h0.y = fmaxf(acc[i][1] + bia[1], 0.f);
            h0.z = fmaxf(acc[i][2] + bia[2], 0.f);
            h0.w = fmaxf(acc[i][3] + bia[3], 0.f);
            h1v.x = fmaxf(acc[i][4] + bia[4], 0.f);
            h1v.y = fmaxf(acc[i][5] + bia[5], 0.f);
            h1v.z = fmaxf(acc[i][6] + bia[6], 0.f);
            h1v.w = fmaxf(acc[i][7] + bia[7], 0.f);
            ((float4*)(h1sm + m * 256))[lane * 2]     = h0;
            ((float4*)(h1sm + m * 256))[lane * 2 + 1] = h1v;
        }
    }
    __syncthreads();

    // ---- Stage 2: out = h1 @ W2 + b2 + c_last @ Wcc + bcc   M=64 N=128
    float4 acc2[8];
    {
        float4 f2 = ((const float4*)bfc2)[lane];
        float4 fc = ((const float4*)bcc)[lane];
        float4 bs = make_float4(f2.x + fc.x, f2.y + fc.y, f2.z + fc.z, f2.w + fc.w);
#pragma unroll
        for (int i = 0; i < 8; ++i) acc2[i] = bs;
    }
#pragma unroll 1
    for (int kc = 0; kc < 256; kc += 32) {
        const float4* src = (const float4*)(w2 + (size_t)kc * 128);
#pragma unroll
        for (int i = 0; i < 4; ++i) ((float4*)wsm)[tid + 256 * i] = src[tid + 256 * i];
        __syncthreads();
#pragma unroll 8
        for (int k = 0; k < 32; ++k) {
            float a[8];
#pragma unroll
            for (int i = 0; i < 8; ++i) a[i] = h1sm[(warp * 8 + i) * 256 + kc + k];
            float4 bv = ((const float4*)(wsm + k * 128))[lane];
#pragma unroll
            for (int i = 0; i < 8; ++i) {
                acc2[i].x += a[i] * bv.x; acc2[i].y += a[i] * bv.y;
                acc2[i].z += a[i] * bv.z; acc2[i].w += a[i] * bv.w;
            }
        }
        __syncthreads();
    }
    // c_last @ Wcc in two K-chunks of 32 (wsm is 16KB)
#pragma unroll 1
    for (int kc = 0; kc < 64; kc += 32) {
        const float4* src = (const float4*)(wcc + (size_t)kc * 128);
#pragma unroll
        for (int i = 0; i < 4; ++i) ((float4*)wsm)[tid + 256 * i] = src[tid + 256 * i];
        __syncthreads();
#pragma unroll 8
        for (int k = 0; k < 32; ++k) {
            float a[8];
#pragma unroll
            for (int i = 0; i < 8; ++i) a[i] = clsm[(warp * 8 + i) * 64 + kc + k];
            float4 bv = ((const float4*)(wsm + k * 128))[lane];
#pragma unroll
            for (int i = 0; i < 8; ++i) {
                acc2[i].x += a[i] * bv.x; acc2[i].y += a[i] * bv.y;
                acc2[i].z += a[i] * bv.z; acc2[i].w += a[i] * bv.w;
            }
        }
        __syncthreads();
    }

    // ---- epilogue: write c, scatter-add sums
#pragma unroll
    for (int i = 0; i < 8; ++i) {
        int pt = warp * 8 + i, n = n0 + pt;
        if (n < NP) {
            reinterpret_cast<float4*>(c_out + ((size_t)b * NP + n) * COUTN)[lane] = acc2[i];
            float* s = g_sums + ((size_t)(b * HW + pidx[pt])) * COUTN + lane * 4;
            atomicAdd(s + 0, acc2[i].x);
            atomicAdd(s + 1, acc2[i].y);
            atomicAdd(s + 2, acc2[i].z);
            atomicAdd(s + 3, acc2[i].w);
        }
    }
}

// =====================================================================
// finalize: plane = sums / max(cnt,1), transpose to NCHW (before_pool),
// fused 2x2 maxpool (out).
// =====================================================================
__global__ __launch_bounds__(256) void finalize_kernel(
    float* __restrict__ out, float* __restrict__ before)
{
    __shared__ float sd[128][33];
    __shared__ float csm[128];
    const int tid = threadIdx.x;
    const int x0  = blockIdx.x * 64;
    const int y0  = blockIdx.y * 2;
    const int b   = blockIdx.z >> 2;
    const int cg  = blockIdx.z & 3;

    if (tid < 128) {
        int gpos = (y0 + (tid >> 6)) * 256 + x0 + (tid & 63);
        csm[tid] = fmaxf(g_cnt[b * HW + gpos], 1.f);
    }
    __syncthreads();
#pragma unroll
    for (int i = 0; i < 16; ++i) {
        int lin = tid + 256 * i;
        int pos = lin >> 5, ch = lin & 31;
        int gpos = (y0 + (pos >> 6)) * 256 + x0 + (pos & 63);
        sd[pos][ch] = g_sums[((size_t)(b * HW) + gpos) * COUTN + cg * 32 + ch] / csm[pos];
    }
    __syncthreads();
#pragma unroll
    for (int i = 0; i < 16; ++i) {
        int lin = tid + 256 * i;
        int ch = lin >> 7, pos = lin & 127;
        before[((size_t)(b * COUTN + cg * 32 + ch)) * HW +
               (y0 + (pos >> 6)) * 256 + x0 + (pos & 63)] = sd[pos][ch];
    }
    const int oy = y0 >> 1, ox0 = x0 >> 1;
#pragma unroll
    for (int i = 0; i < 4; ++i) {
        int lin = tid + 256 * i;
        int ch = lin >> 5, ox = lin & 31;
        float m = fmaxf(fmaxf(sd[2 * ox][ch], sd[2 * ox + 1][ch]),
                        fmaxf(sd[64 + 2 * ox][ch], sd[64 + 2 * ox + 1][ch]));
        out[((size_t)(b * COUTN + cg * 32 + ch)) * (128 * 128) + oy * 128 + ox0 + ox] = m;
    }
}

// =====================================================================
// launch
// =====================================================================
extern "C" void kernel_launch(void* const* d_in, const int* in_sizes, int n_in,
                              void* d_out, int out_size)
{
    const float* p      = (const float*)d_in[0];
    const float* x_xy   = (const float*)d_in[1];
    const float* x2     = (const float*)d_in[2];
    const float* c_last = (const float*)d_in[3];
    const float* w1c    = (const float*)d_in[4];
    const float* b1c    = (const float*)d_in[5];
    const float* w2c    = (const float*)d_in[6];
    const float* b2c    = (const float*)d_in[7];
    const float* w11    = (const float*)d_in[8];
    const float* b11    = (const float*)d_in[9];
    const float* wf1    = (const float*)d_in[10];
    const float* bf1    = (const float*)d_in[11];
    const float* wf2    = (const float*)d_in[12];
    const float* bf2    = (const float*)d_in[13];
    const float* wcc    = (const float*)d_in[14];
    const float* bcc    = (const float*)d_in[15];

    float* out    = (float*)d_out;                            // [2,128,128,128]
    float* before = out    + (size_t)BB * COUTN * 128 * 128;  // [2,128,256,256]
    float* xafter = before + (size_t)BB * COUTN * HW;         // [2,128,256,256]
    float* cout   = xafter + (size_t)BB * COUTN * HW;         // [2,100000,128]

    zero_kernel<<<2048, 256>>>();

    dim3 cg(8, 4, BB * 16);
    conv1_kernel<<<cg, 256>>>(x_xy, w1c, b1c);
    conv2_kernel<<<cg, 256>>>(x2, w2c, b2c, w11, b11, xafter);

    cudaFuncSetAttribute(point_kernel, cudaFuncAttributeMaxDynamicSharedMemorySize, PK_SMEM);
    dim3 pg((NP + 63) / 64, BB);
    point_kernel<<<pg, 256, PK_SMEM>>>(p, c_last, wf1, bf1, wf2, bf2, wcc, bcc, cout);

    dim3 fg(4, 128, BB * 4);
    finalize_kernel<<<fg, 256>>>(out, before);
}